// round 9
// baseline (speedup 1.0000x reference)
#include <cuda_runtime.h>
#include <cuda_fp16.h>
#include <cstdint>

// out[32,14336] = (x * scales) @ W^T
//   x: [32,4096] f32, W: [14336,4096] int32 (|w|<=127), scales: [4096] f32
// HBM-bound: 235MB weight stream -> floor ~29.4us.
// R8: exact two-wave split-K. Occupancy capacity = 444 CTAs (3/SM x 148).
// 888 CTAs = exactly 2 full waves; each CTA = 32 outputs x K/2. This removes
// R5's 4-CTA straggler wave (~10us of near-idle chip). K-halves combine via
// atomicAdd into an output zeroed by the prep kernel. Inner loop = R5's
// register double-buffered int4 pipeline (best measured wave-1 behavior).

#define TOKENS 32
#define IN_F   4096
#define OUT_F  14336
#define NUM_KB (IN_F / 16)      // 256 k16-blocks
#define NTILES (OUT_F / 32)     // 448 n-tiles

// A-fragments of xs=x*scales in fp16, fragment-major (permuted k-layout):
// index ((kb*2 + mi)*32 + lane) -> uint4 (8 fp16 = one m16k16 A frag slice)
__device__ uint4 g_xsfrag[NUM_KB * 2 * 32];

// ---------------------------------------------------------------------------
// Prep: build fragment-major fp16 xs with the permuted k-layout AND zero the
// output (needed for the split-K atomicAdd combine).
// lane quad q owns physical k = kb*16 + 4q .. 4q+3 (one contiguous float4).
// ---------------------------------------------------------------------------
__global__ __launch_bounds__(256) void prep_xs_kernel(
    const float* __restrict__ x, const float* __restrict__ scales,
    float* __restrict__ out)
{
    // zero out: 32*14336 floats = 114688 float4 / 16384 threads = 7 each
    {
        int t = blockIdx.x * 256 + threadIdx.x;
        float4 z = make_float4(0.f, 0.f, 0.f, 0.f);
        float4* o4 = (float4*)out;
        #pragma unroll
        for (int i = 0; i < 7; i++) o4[t + i * 16384] = z;
    }

    int wg   = blockIdx.x * (blockDim.x >> 5) + (threadIdx.x >> 5); // 0..511
    int lane = threadIdx.x & 31;
    int kb = wg >> 1;
    int mi = wg & 1;

    int q = lane & 3;        // k-quad
    int g = lane >> 2;       // group row
    int r0 = mi * 16 + g;    // token row
    int r1 = r0 + 8;
    int k0 = kb * 16 + 4 * q;

    float4 s  = *(const float4*)(scales + k0);
    float4 x0 = *(const float4*)(x + r0 * IN_F + k0);
    float4 x1 = *(const float4*)(x + r1 * IN_F + k0);

    __half2 h0 = __floats2half2_rn(x0.x * s.x, x0.y * s.y);
    __half2 h1 = __floats2half2_rn(x1.x * s.x, x1.y * s.y);
    __half2 h2 = __floats2half2_rn(x0.z * s.z, x0.w * s.w);
    __half2 h3 = __floats2half2_rn(x1.z * s.z, x1.w * s.w);

    uint4 v;
    v.x = *(const uint32_t*)&h0;
    v.y = *(const uint32_t*)&h1;
    v.z = *(const uint32_t*)&h2;
    v.w = *(const uint32_t*)&h3;
    g_xsfrag[(kb * 2 + mi) * 32 + lane] = v;
}

// ---------------------------------------------------------------------------
__device__ __forceinline__ void mma16816(float c[4],
    uint32_t a0, uint32_t a1, uint32_t a2, uint32_t a3,
    uint32_t b0, uint32_t b1)
{
    asm volatile(
        "mma.sync.aligned.m16n8k16.row.col.f32.f16.f16.f32 "
        "{%0,%1,%2,%3}, {%4,%5,%6,%7}, {%8,%9}, {%0,%1,%2,%3};\n"
        : "+f"(c[0]), "+f"(c[1]), "+f"(c[2]), "+f"(c[3])
        : "r"(a0), "r"(a1), "r"(a2), "r"(a3), "r"(b0), "r"(b1));
}

__device__ __forceinline__ uint32_t pack_w_h2(int w0, int w1)
{
    __half2 h = __halves2half2(__int2half_rn(w0), __int2half_rn(w1));
    return *(const uint32_t*)&h;
}

#define NWARPS 8
#define NSPLIT 2
#define KSTEPS (NUM_KB / NWARPS / NSPLIT)   // 16 k16-steps per warp

// ---------------------------------------------------------------------------
// GEMM: 888 CTAs x 256 threads (2 exact waves). CTA = one n-tile (32 outputs)
// x one K-half (2048); 8 warps split the K-half.
// ---------------------------------------------------------------------------
__global__ void __launch_bounds__(256, 3) gemm_q8_kernel(
    const int* __restrict__ W, float* __restrict__ out)
{
    const int lane = threadIdx.x & 31;
    const int warp = threadIdx.x >> 5;    // 0..7, splits the K-half

    const int bid  = blockIdx.x;
    const int ksp  = (bid >= NTILES) ? 1 : 0;
    const int tile = bid - ksp * NTILES;  // 0..447
    const int n0   = tile * 32;           // output-feature tile base

    const int q = lane & 3;
    const int g = lane >> 2;

    // accumulators: [mi(2)][nfrag(4)][4]
    float c[2][4][4];
    #pragma unroll
    for (int a = 0; a < 2; a++)
        #pragma unroll
        for (int b = 0; b < 4; b++)
            #pragma unroll
            for (int d = 0; d < 4; d++) c[a][b][d] = 0.0f;

    const int kb0 = ksp * (NUM_KB / NSPLIT) + warp * KSTEPS;

    // weight base: row = n0 + g (+ j*8), col = 4q (+ kb*16) -- one int4/lane
    const int* wrow = W + (size_t)(n0 + g) * IN_F + 4 * q;

    // ---- software pipeline: current buffers ----
    uint4 A0c, A1c;
    int4  wc[4];
    {
        const int kofs = kb0 * 16;
        A0c = g_xsfrag[(kb0 * 2 + 0) * 32 + lane];
        A1c = g_xsfrag[(kb0 * 2 + 1) * 32 + lane];
        #pragma unroll
        for (int j = 0; j < 4; j++)
            wc[j] = *(const int4*)(wrow + (size_t)j * 8 * IN_F + kofs);
    }

    #pragma unroll 2
    for (int ks = 0; ks < KSTEPS; ks++) {
        // prefetch next iteration (clamped on last iter -> L1-hit reload)
        const int ksn  = (ks + 1 < KSTEPS) ? (ks + 1) : ks;
        const int kbn  = kb0 + ksn;
        const int kofn = kbn * 16;

        uint4 A0n = g_xsfrag[(kbn * 2 + 0) * 32 + lane];
        uint4 A1n = g_xsfrag[(kbn * 2 + 1) * 32 + lane];
        int4  wn[4];
        #pragma unroll
        for (int j = 0; j < 4; j++)
            wn[j] = *(const int4*)(wrow + (size_t)j * 8 * IN_F + kofn);

        // compute on current buffers
        #pragma unroll
        for (int j = 0; j < 4; j++) {
            uint32_t b0 = pack_w_h2(wc[j].x, wc[j].y);
            uint32_t b1 = pack_w_h2(wc[j].z, wc[j].w);
            mma16816(c[0][j], A0c.x, A0c.y, A0c.z, A0c.w, b0, b1);
            mma16816(c[1][j], A1c.x, A1c.y, A1c.z, A1c.w, b0, b1);
        }

        // rotate buffers
        A0c = A0n; A1c = A1n;
        #pragma unroll
        for (int j = 0; j < 4; j++) wc[j] = wn[j];
    }

    // cross-warp K reduction through smem (8 partials)
    __shared__ float red[NWARPS][TOKENS][32];
    #pragma unroll
    for (int mi = 0; mi < 2; mi++) {
        #pragma unroll
        for (int j = 0; j < 4; j++) {
            int row = mi * 16 + g;
            int col = j * 8 + 2 * q;
            *(float2*)&red[warp][row][col]     = make_float2(c[mi][j][0], c[mi][j][1]);
            *(float2*)&red[warp][row + 8][col] = make_float2(c[mi][j][2], c[mi][j][3]);
        }
    }
    __syncthreads();

    // 256 threads: each combines 4 (row,col) outputs via atomicAdd (split-K)
    const int col   = threadIdx.x & 31;
    const int rbase = (threadIdx.x >> 5) * 4;
    #pragma unroll
    for (int i = 0; i < 4; i++) {
        int row = rbase + i;
        float v = 0.0f;
        #pragma unroll
        for (int w = 0; w < NWARPS; w++) v += red[w][row][col];
        atomicAdd(&out[(size_t)row * OUT_F + n0 + col], v);
    }
}

// ---------------------------------------------------------------------------
extern "C" void kernel_launch(void* const* d_in, const int* in_sizes, int n_in,
                              void* d_out, int out_size)
{
    const float* x      = (const float*)d_in[0];
    const int*   weight = (const int*)d_in[1];
    const float* scales = (const float*)d_in[2];
    float*       out    = (float*)d_out;

    prep_xs_kernel<<<64, 256>>>(x, scales, out);
    gemm_q8_kernel<<<NTILES * NSPLIT, 256>>>(weight, out);
}

// round 11
// speedup vs baseline: 1.1344x; 1.1344x over previous
#include <cuda_runtime.h>
#include <cuda_fp16.h>
#include <cstdint>

// out[32,14336] = (x * scales) @ W^T
//   x: [32,4096] f32, W: [14336,4096] int32 (|w|<=127), scales: [4096] f32
// HBM-bound: 235MB weight stream -> floor ~29.4us.
// R9: single perfectly-balanced wave. 444 CTAs (=3/SM x 148). Work = flattened
// (tile, kb-unit) space: 448 tiles x 32 units = 14336 units; CTA gets 32 or 33
// contiguous units (<=2 tile segments). Inner loop = R5's register
// double-buffered int4 pipeline. Segments end with smem-reduce + atomicAdd
// into an output zeroed by prep. This removes R5's 4-CTA straggler wave
// (~7us of near-idle chip) without shortening the pipeline (R8's mistake).

#define TOKENS 32
#define IN_F   4096
#define OUT_F  14336
#define NUM_KB (IN_F / 16)      // 256 k16-blocks
#define NTILES (OUT_F / 32)     // 448 n-tiles
#define UNITS_PER_TILE 32       // one kb per warp per unit (8 kb/unit)
#define TOTAL_UNITS (NTILES * UNITS_PER_TILE)   // 14336
#define GRID 444                // 3 CTAs/SM x 148 SMs: exactly one wave
#define REM  (TOTAL_UNITS - GRID * 32)          // 128 CTAs carry +1 unit

// A-fragments of xs=x*scales in fp16, fragment-major (permuted k-layout):
// index ((kb*2 + mi)*32 + lane) -> uint4 (8 fp16 = one m16k16 A frag slice)
__device__ uint4 g_xsfrag[NUM_KB * 2 * 32];

// ---------------------------------------------------------------------------
// Prep: build fragment-major fp16 xs (permuted k-layout) AND zero the output.
// ---------------------------------------------------------------------------
__global__ __launch_bounds__(256) void prep_xs_kernel(
    const float* __restrict__ x, const float* __restrict__ scales,
    float* __restrict__ out)
{
    // zero out: 32*14336 floats = 114688 float4 / 16384 threads = 7 each
    {
        int t = blockIdx.x * 256 + threadIdx.x;
        float4 z = make_float4(0.f, 0.f, 0.f, 0.f);
        float4* o4 = (float4*)out;
        #pragma unroll
        for (int i = 0; i < 7; i++) o4[t + i * 16384] = z;
    }

    int wg   = blockIdx.x * (blockDim.x >> 5) + (threadIdx.x >> 5); // 0..511
    int lane = threadIdx.x & 31;
    int kb = wg >> 1;
    int mi = wg & 1;

    int q = lane & 3;
    int g = lane >> 2;
    int r0 = mi * 16 + g;
    int r1 = r0 + 8;
    int k0 = kb * 16 + 4 * q;

    float4 s  = *(const float4*)(scales + k0);
    float4 x0 = *(const float4*)(x + r0 * IN_F + k0);
    float4 x1 = *(const float4*)(x + r1 * IN_F + k0);

    __half2 h0 = __floats2half2_rn(x0.x * s.x, x0.y * s.y);
    __half2 h1 = __floats2half2_rn(x1.x * s.x, x1.y * s.y);
    __half2 h2 = __floats2half2_rn(x0.z * s.z, x0.w * s.w);
    __half2 h3 = __floats2half2_rn(x1.z * s.z, x1.w * s.w);

    uint4 v;
    v.x = *(const uint32_t*)&h0;
    v.y = *(const uint32_t*)&h1;
    v.z = *(const uint32_t*)&h2;
    v.w = *(const uint32_t*)&h3;
    g_xsfrag[(kb * 2 + mi) * 32 + lane] = v;
}

// ---------------------------------------------------------------------------
__device__ __forceinline__ void mma16816(float c[4],
    uint32_t a0, uint32_t a1, uint32_t a2, uint32_t a3,
    uint32_t b0, uint32_t b1)
{
    asm volatile(
        "mma.sync.aligned.m16n8k16.row.col.f32.f16.f16.f32 "
        "{%0,%1,%2,%3}, {%4,%5,%6,%7}, {%8,%9}, {%0,%1,%2,%3};\n"
        : "+f"(c[0]), "+f"(c[1]), "+f"(c[2]), "+f"(c[3])
        : "r"(a0), "r"(a1), "r"(a2), "r"(a3), "r"(b0), "r"(b1));
}

__device__ __forceinline__ uint32_t pack_w_h2(int w0, int w1)
{
    __half2 h = __halves2half2(__int2half_rn(w0), __int2half_rn(w1));
    return *(const uint32_t*)&h;
}

#define NWARPS 8

// ---------------------------------------------------------------------------
// GEMM: 444 CTAs x 256 threads, one balanced wave.
// ---------------------------------------------------------------------------
__global__ void __launch_bounds__(256, 3) gemm_q8_kernel(
    const int* __restrict__ W, float* __restrict__ out)
{
    const int lane = threadIdx.x & 31;
    const int warp = threadIdx.x >> 5;    // 0..7
    const int bid  = blockIdx.x;

    const int q = lane & 3;
    const int g = lane >> 2;

    __shared__ float red[NWARPS][TOKENS][32];

    // contiguous flattened unit range for this CTA
    int u         = bid * 32 + (bid < REM ? bid : REM);
    int remaining = 32 + (bid < REM ? 1 : 0);

    // accumulators: [mi(2)][nfrag(4)][4]
    float c[2][4][4];
    #pragma unroll
    for (int a = 0; a < 2; a++)
        #pragma unroll
        for (int b = 0; b < 4; b++)
            #pragma unroll
            for (int d = 0; d < 4; d++) c[a][b][d] = 0.0f;

    while (remaining > 0) {
        const int tile   = u >> 5;            // u / 32
        const int ut0    = u & 31;            // first unit within tile
        const int seglen = min(remaining, 32 - ut0);
        const int n0     = tile * 32;

        // weight base: row = n0 + g (+ j*8), col = 4q (+ kb*16)
        const int* wrow = W + (size_t)(n0 + g) * IN_F + 4 * q;

        // warp's kb for unit index i: kb = (ut0 + i)*8 + warp
        int kb_c = ut0 * 8 + warp;

        // ---- software pipeline: fill current buffers ----
        uint4 A0c = g_xsfrag[(kb_c * 2 + 0) * 32 + lane];
        uint4 A1c = g_xsfrag[(kb_c * 2 + 1) * 32 + lane];
        int4  wc[4];
        {
            const int kofs = kb_c * 16;
            #pragma unroll
            for (int j = 0; j < 4; j++)
                wc[j] = *(const int4*)(wrow + (size_t)j * 8 * IN_F + kofs);
        }

        #pragma unroll 2
        for (int i = 0; i < seglen; i++) {
            // prefetch next unit (clamped at segment end -> L1-hit reload)
            const int i_n  = (i + 1 < seglen) ? (i + 1) : i;
            const int kb_n = (ut0 + i_n) * 8 + warp;
            const int kofn = kb_n * 16;

            uint4 A0n = g_xsfrag[(kb_n * 2 + 0) * 32 + lane];
            uint4 A1n = g_xsfrag[(kb_n * 2 + 1) * 32 + lane];
            int4  wn[4];
            #pragma unroll
            for (int j = 0; j < 4; j++)
                wn[j] = *(const int4*)(wrow + (size_t)j * 8 * IN_F + kofn);

            // compute on current buffers
            #pragma unroll
            for (int j = 0; j < 4; j++) {
                uint32_t b0 = pack_w_h2(wc[j].x, wc[j].y);
                uint32_t b1 = pack_w_h2(wc[j].z, wc[j].w);
                mma16816(c[0][j], A0c.x, A0c.y, A0c.z, A0c.w, b0, b1);
                mma16816(c[1][j], A1c.x, A1c.y, A1c.z, A1c.w, b0, b1);
            }

            A0c = A0n; A1c = A1n;
            #pragma unroll
            for (int j = 0; j < 4; j++) wc[j] = wn[j];
        }

        // ---- segment epilogue: cross-warp reduce + atomic combine ----
        #pragma unroll
        for (int mi = 0; mi < 2; mi++) {
            #pragma unroll
            for (int j = 0; j < 4; j++) {
                int row = mi * 16 + g;
                int col = j * 8 + 2 * q;
                *(float2*)&red[warp][row][col]     = make_float2(c[mi][j][0], c[mi][j][1]);
                *(float2*)&red[warp][row + 8][col] = make_float2(c[mi][j][2], c[mi][j][3]);
            }
        }
        __syncthreads();

        {
            const int col   = threadIdx.x & 31;
            const int rbase = (threadIdx.x >> 5) * 4;
            #pragma unroll
            for (int i = 0; i < 4; i++) {
                int row = rbase + i;
                float v = 0.0f;
                #pragma unroll
                for (int w = 0; w < NWARPS; w++) v += red[w][row][col];
                atomicAdd(&out[(size_t)row * OUT_F + n0 + col], v);
            }
        }

        u         += seglen;
        remaining -= seglen;

        if (remaining > 0) {
            __syncthreads();   // protect red before next segment reuses it
            #pragma unroll
            for (int a = 0; a < 2; a++)
                #pragma unroll
                for (int b = 0; b < 4; b++)
                    #pragma unroll
                    for (int d = 0; d < 4; d++) c[a][b][d] = 0.0f;
        }
    }
}

// ---------------------------------------------------------------------------
extern "C" void kernel_launch(void* const* d_in, const int* in_sizes, int n_in,
                              void* d_out, int out_size)
{
    const float* x      = (const float*)d_in[0];
    const int*   weight = (const int*)d_in[1];
    const float* scales = (const float*)d_in[2];
    float*       out    = (float*)d_out;

    prep_xs_kernel<<<64, 256>>>(x, scales, out);
    gemm_q8_kernel<<<GRID, 256>>>(weight, out);
}

// round 13
// speedup vs baseline: 1.1788x; 1.0391x over previous
#include <cuda_runtime.h>
#include <cuda_fp16.h>
#include <cstdint>

// out[32,14336] = (x * scales) @ W^T
//   x: [32,4096] f32, W: [14336,4096] int32 (|w|<=127), scales: [4096] f32
// HBM-bound: 235MB weight stream -> floor ~29.4us.
// R11: smem-staged W. Every direct-LDG scheme converged at ~67-72% DRAM
// because the B-fragment needs 8 n-rows per load -> 8 L1tex wavefronts per
// 512B. Now a CTA-cooperative cp.async ring loads W fully coalesced (4 lines
// per warp-instr, 128B used per line, halving wavefronts), and warps read
// fragments from smem with conflict-free LDS.128 (576B pitch). 3-deep ring,
// 1 barrier/stage, 2 stages in flight. Epilogue = direct store (R5).

#define TOKENS 32
#define IN_F   4096
#define OUT_F  14336
#define NUM_KB (IN_F / 16)        // 256 k16-blocks
#define NWARPS 8
#define NSTAGES (NUM_KB / NWARPS) // 32 stages; stage = 8 kb (one per warp)

#define PITCH 576                  // stage row pitch: 512B data + 64B pad
#define STAGE_BYTES (32 * PITCH)   // 18432 B
#define NBUF 3
#define SMEM_TOTAL (NBUF * STAGE_BYTES)   // 55296 B (red overlays)

// A-fragments of xs=x*scales in fp16, fragment-major (permuted k-layout):
// index ((kb*2 + mi)*32 + lane) -> uint4 (8 fp16 = one m16k16 A frag slice)
__device__ uint4 g_xsfrag[NUM_KB * 2 * 32];

// ---------------------------------------------------------------------------
// Prep: build fragment-major fp16 xs with the permuted k-layout.
// lane quad q owns physical k = kb*16 + 4q .. 4q+3 (one contiguous float4).
// ---------------------------------------------------------------------------
__global__ __launch_bounds__(256) void prep_xs_kernel(
    const float* __restrict__ x, const float* __restrict__ scales)
{
    int wg   = blockIdx.x * (blockDim.x >> 5) + (threadIdx.x >> 5); // 0..511
    int lane = threadIdx.x & 31;
    int kb = wg >> 1;
    int mi = wg & 1;

    int q = lane & 3;
    int g = lane >> 2;
    int r0 = mi * 16 + g;
    int r1 = r0 + 8;
    int k0 = kb * 16 + 4 * q;

    float4 s  = *(const float4*)(scales + k0);
    float4 x0 = *(const float4*)(x + r0 * IN_F + k0);
    float4 x1 = *(const float4*)(x + r1 * IN_F + k0);

    __half2 h0 = __floats2half2_rn(x0.x * s.x, x0.y * s.y);
    __half2 h1 = __floats2half2_rn(x1.x * s.x, x1.y * s.y);
    __half2 h2 = __floats2half2_rn(x0.z * s.z, x0.w * s.w);
    __half2 h3 = __floats2half2_rn(x1.z * s.z, x1.w * s.w);

    uint4 v;
    v.x = *(const uint32_t*)&h0;
    v.y = *(const uint32_t*)&h1;
    v.z = *(const uint32_t*)&h2;
    v.w = *(const uint32_t*)&h3;
    g_xsfrag[(kb * 2 + mi) * 32 + lane] = v;
}

// ---------------------------------------------------------------------------
__device__ __forceinline__ void mma16816(float c[4],
    uint32_t a0, uint32_t a1, uint32_t a2, uint32_t a3,
    uint32_t b0, uint32_t b1)
{
    asm volatile(
        "mma.sync.aligned.m16n8k16.row.col.f32.f16.f16.f32 "
        "{%0,%1,%2,%3}, {%4,%5,%6,%7}, {%8,%9}, {%0,%1,%2,%3};\n"
        : "+f"(c[0]), "+f"(c[1]), "+f"(c[2]), "+f"(c[3])
        : "r"(a0), "r"(a1), "r"(a2), "r"(a3), "r"(b0), "r"(b1));
}

__device__ __forceinline__ uint32_t pack_w_h2(int w0, int w1)
{
    __half2 h = __halves2half2(__int2half_rn(w0), __int2half_rn(w1));
    return *(const uint32_t*)&h;
}

__device__ __forceinline__ void cp_async16(uint32_t dst_smem, const void* src)
{
    asm volatile("cp.async.cg.shared.global [%0], [%1], 16;\n"
                 :: "r"(dst_smem), "l"(src));
}
#define CP_COMMIT() asm volatile("cp.async.commit_group;\n" ::: "memory")
#define CP_WAIT1()  asm volatile("cp.async.wait_group 1;\n" ::: "memory")
#define CP_WAIT0()  asm volatile("cp.async.wait_group 0;\n" ::: "memory")

// ---------------------------------------------------------------------------
// GEMM: 448 CTAs x 256 threads, occ 3. CTA = 32 output rows x full K.
// Stage s: smem tile = 32 rows x 128 ints (k in [s*128, s*128+128)).
// Warp w consumes kb = s*8 + w from the tile.
// ---------------------------------------------------------------------------
__global__ void __launch_bounds__(256, 3) gemm_q8_kernel(
    const int* __restrict__ W, float* __restrict__ out)
{
    extern __shared__ char smem_raw[];
    const uint32_t smem_base = (uint32_t)__cvta_generic_to_shared(smem_raw);

    const int tid  = threadIdx.x;
    const int lane = tid & 31;
    const int warp = tid >> 5;            // 0..7
    const int n0   = blockIdx.x * 32;

    const int q = lane & 3;
    const int g = lane >> 2;

    // cp.async geometry: thread t loads row r = t>>3, 4 chunks of 16B at
    // int-cols (t&7)*4 + {0,32,64,96} within the stage's 128-int span.
    const int r_ld  = tid >> 3;           // 0..31
    const int c_ld  = (tid & 7) * 4;      // int col base
    const int* gsrc = W + (size_t)(n0 + r_ld) * IN_F + c_ld;
    const uint32_t sdst = smem_base + r_ld * PITCH + (tid & 7) * 16;

    // accumulators
    float c[2][4][4];
    #pragma unroll
    for (int a = 0; a < 2; a++)
        #pragma unroll
        for (int b = 0; b < 4; b++)
            #pragma unroll
            for (int d = 0; d < 4; d++) c[a][b][d] = 0.0f;

    // ---- prologue: prime 2 stages ----
    #pragma unroll
    for (int s = 0; s < 2; s++) {
        const int* src = gsrc + s * 128;
        uint32_t d = sdst + s * STAGE_BYTES;  // (s % NBUF) == s here
        cp_async16(d,       src);
        cp_async16(d + 128, src + 32);
        cp_async16(d + 256, src + 64);
        cp_async16(d + 384, src + 96);
        CP_COMMIT();
    }

    // A fragments for stage 0 (kb = warp)
    uint4 A0c = g_xsfrag[(warp * 2 + 0) * 32 + lane];
    uint4 A1c = g_xsfrag[(warp * 2 + 1) * 32 + lane];

    // fragment read base: row (g+8j), col warp*64 + q*16
    const uint32_t frag_base = smem_base + g * PITCH + warp * 64 + q * 16;

    for (int s = 0; s < NSTAGES; s++) {
        // stage s data ready (stage s+1 may still be pending)
        if (s == NSTAGES - 1) { CP_WAIT0(); } else { CP_WAIT1(); }
        __syncthreads();   // also: all warps finished reading buf[(s-1)%3]

        // issue stage s+2 into buf[(s+2)%3] (safe: last read at iter s-1)
        if (s + 2 < NSTAGES) {
            const int sp = s + 2;
            const int* src = gsrc + sp * 128;
            uint32_t d = sdst + (sp % NBUF) * STAGE_BYTES;
            cp_async16(d,       src);
            cp_async16(d + 128, src + 32);
            cp_async16(d + 256, src + 64);
            cp_async16(d + 384, src + 96);
            CP_COMMIT();
        }

        // prefetch A for stage s+1 (register one-ahead)
        const int sn  = (s + 1 < NSTAGES) ? (s + 1) : s;
        const int kbn = sn * 8 + warp;
        uint4 A0n = g_xsfrag[(kbn * 2 + 0) * 32 + lane];
        uint4 A1n = g_xsfrag[(kbn * 2 + 1) * 32 + lane];

        // compute: read B-fragments from smem, 8 MMAs
        const uint32_t buf = frag_base + (s % NBUF) * STAGE_BYTES;
        #pragma unroll
        for (int j = 0; j < 4; j++) {
            int4 wv;
            asm volatile("ld.shared.v4.b32 {%0,%1,%2,%3}, [%4];\n"
                         : "=r"(wv.x), "=r"(wv.y), "=r"(wv.z), "=r"(wv.w)
                         : "r"(buf + j * (8 * PITCH)));
            uint32_t b0 = pack_w_h2(wv.x, wv.y);
            uint32_t b1 = pack_w_h2(wv.z, wv.w);
            mma16816(c[0][j], A0c.x, A0c.y, A0c.z, A0c.w, b0, b1);
            mma16816(c[1][j], A1c.x, A1c.y, A1c.z, A1c.w, b0, b1);
        }

        A0c = A0n; A1c = A1n;
    }

    // ---- cross-warp K reduction: overlay red on the staging smem ----
    __syncthreads();
    float (*red)[TOKENS][32] = (float (*)[TOKENS][32])smem_raw;
    #pragma unroll
    for (int mi = 0; mi < 2; mi++) {
        #pragma unroll
        for (int j = 0; j < 4; j++) {
            int row = mi * 16 + g;
            int col = j * 8 + 2 * q;
            *(float2*)&red[warp][row][col]     = make_float2(c[mi][j][0], c[mi][j][1]);
            *(float2*)&red[warp][row + 8][col] = make_float2(c[mi][j][2], c[mi][j][3]);
        }
    }
    __syncthreads();

    // 256 threads: each stores 4 (row,col) outputs
    const int col   = tid & 31;
    const int rbase = (tid >> 5) * 4;
    #pragma unroll
    for (int i = 0; i < 4; i++) {
        int row = rbase + i;
        float v = 0.0f;
        #pragma unroll
        for (int w = 0; w < NWARPS; w++) v += red[w][row][col];
        out[(size_t)row * OUT_F + n0 + col] = v;
    }
}

// ---------------------------------------------------------------------------
extern "C" void kernel_launch(void* const* d_in, const int* in_sizes, int n_in,
                              void* d_out, int out_size)
{
    const float* x      = (const float*)d_in[0];
    const int*   weight = (const int*)d_in[1];
    const float* scales = (const float*)d_in[2];
    float*       out    = (float*)d_out;

    cudaFuncSetAttribute(gemm_q8_kernel,
                         cudaFuncAttributeMaxDynamicSharedMemorySize, SMEM_TOTAL);

    prep_xs_kernel<<<64, 256>>>(x, scales);
    gemm_q8_kernel<<<OUT_F / 32, 256, SMEM_TOTAL>>>(weight, out);
}

// round 14
// speedup vs baseline: 1.1972x; 1.0156x over previous
#include <cuda_runtime.h>
#include <cuda_fp16.h>
#include <cstdint>

// out[32,14336] = (x * scales) @ W^T
//   x: [32,4096] f32, W: [14336,4096] int32 (|w|<=127), scales: [4096] f32
// HBM-bound: 235MB weight stream -> floor ~29.4us.
// R13: R5 inner loop (best measured: gemm 41.7us @ 72% DRAM; all structural
// alternatives -- balanced waves, cp.async staging, smem rings -- measured
// WORSE) + PDL overlap: gemm launches programmatically-dependent on prep, so
// its W-prefetch prologue runs under prep's tail and the ~4us prep+launch gap
// leaves the critical path. griddepcontrol.wait guards only the A-frag reads.

#define TOKENS 32
#define IN_F   4096
#define OUT_F  14336
#define NUM_KB (IN_F / 16)      // 256 k16-blocks

// A-fragments of xs=x*scales in fp16, fragment-major (permuted k-layout):
// index ((kb*2 + mi)*32 + lane) -> uint4 (8 fp16 = one m16k16 A frag slice)
__device__ uint4 g_xsfrag[NUM_KB * 2 * 32];

// ---------------------------------------------------------------------------
// Prep: build fragment-major fp16 xs with the permuted k-layout.
// lane quad q owns physical k = kb*16 + 4q .. 4q+3 (one contiguous float4).
// ---------------------------------------------------------------------------
__global__ __launch_bounds__(256) void prep_xs_kernel(
    const float* __restrict__ x, const float* __restrict__ scales)
{
    int wg   = blockIdx.x * (blockDim.x >> 5) + (threadIdx.x >> 5); // 0..511
    int lane = threadIdx.x & 31;
    int kb = wg >> 1;
    int mi = wg & 1;

    int q = lane & 3;        // k-quad
    int g = lane >> 2;       // group row
    int r0 = mi * 16 + g;    // token row
    int r1 = r0 + 8;
    int k0 = kb * 16 + 4 * q;

    float4 s  = *(const float4*)(scales + k0);
    float4 x0 = *(const float4*)(x + r0 * IN_F + k0);
    float4 x1 = *(const float4*)(x + r1 * IN_F + k0);

    __half2 h0 = __floats2half2_rn(x0.x * s.x, x0.y * s.y);
    __half2 h1 = __floats2half2_rn(x1.x * s.x, x1.y * s.y);
    __half2 h2 = __floats2half2_rn(x0.z * s.z, x0.w * s.w);
    __half2 h3 = __floats2half2_rn(x1.z * s.z, x1.w * s.w);

    uint4 v;
    v.x = *(const uint32_t*)&h0;
    v.y = *(const uint32_t*)&h1;
    v.z = *(const uint32_t*)&h2;
    v.w = *(const uint32_t*)&h3;
    g_xsfrag[(kb * 2 + mi) * 32 + lane] = v;

    // allow dependent grid (gemm) to launch; its A-frag reads are gated by
    // griddepcontrol.wait, which guarantees visibility of the store above.
    asm volatile("griddepcontrol.launch_dependents;");
}

// ---------------------------------------------------------------------------
__device__ __forceinline__ void mma16816(float c[4],
    uint32_t a0, uint32_t a1, uint32_t a2, uint32_t a3,
    uint32_t b0, uint32_t b1)
{
    asm volatile(
        "mma.sync.aligned.m16n8k16.row.col.f32.f16.f16.f32 "
        "{%0,%1,%2,%3}, {%4,%5,%6,%7}, {%8,%9}, {%0,%1,%2,%3};\n"
        : "+f"(c[0]), "+f"(c[1]), "+f"(c[2]), "+f"(c[3])
        : "r"(a0), "r"(a1), "r"(a2), "r"(a3), "r"(b0), "r"(b1));
}

__device__ __forceinline__ uint32_t pack_w_h2(int w0, int w1)
{
    __half2 h = __halves2half2(__int2half_rn(w0), __int2half_rn(w1));
    return *(const uint32_t*)&h;
}

#define NWARPS 8
#define KSTEPS (NUM_KB / NWARPS)   // 32 k16-steps per warp

// ---------------------------------------------------------------------------
// GEMM: 448 CTAs x 256 threads, occ 3. CTA owns 32 output features; 8 warps
// split K. Register double-buffered int4 W pipeline (R5).
// ---------------------------------------------------------------------------
__global__ void __launch_bounds__(256, 3) gemm_q8_kernel(
    const int* __restrict__ W, float* __restrict__ out)
{
    const int lane = threadIdx.x & 31;
    const int warp = threadIdx.x >> 5;    // 0..7, splits K
    const int n0   = blockIdx.x * 32;     // output-feature tile base

    const int q = lane & 3;
    const int g = lane >> 2;

    // accumulators: [mi(2)][nfrag(4)][4]
    float c[2][4][4];
    #pragma unroll
    for (int a = 0; a < 2; a++)
        #pragma unroll
        for (int b = 0; b < 4; b++)
            #pragma unroll
            for (int d = 0; d < 4; d++) c[a][b][d] = 0.0f;

    const int kb0 = warp * KSTEPS;

    // weight base: row = n0 + g (+ j*8), col = 4q (+ kb*16) -- one int4/lane
    const int* wrow = W + (size_t)(n0 + g) * IN_F + 4 * q;

    // ---- pre-dependency prologue: start the W stream immediately ----
    int4 wc[4];
    {
        const int kofs = kb0 * 16;
        #pragma unroll
        for (int j = 0; j < 4; j++)
            wc[j] = *(const int4*)(wrow + (size_t)j * 8 * IN_F + kofs);
    }

    // wait for prep's A-fragment stores to be visible
    asm volatile("griddepcontrol.wait;" ::: "memory");

    uint4 A0c = g_xsfrag[(kb0 * 2 + 0) * 32 + lane];
    uint4 A1c = g_xsfrag[(kb0 * 2 + 1) * 32 + lane];

    #pragma unroll 2
    for (int ks = 0; ks < KSTEPS; ks++) {
        // prefetch next iteration (clamped on last iter -> L1-hit reload)
        const int ksn  = (ks + 1 < KSTEPS) ? (ks + 1) : ks;
        const int kbn  = kb0 + ksn;
        const int kofn = kbn * 16;

        uint4 A0n = g_xsfrag[(kbn * 2 + 0) * 32 + lane];
        uint4 A1n = g_xsfrag[(kbn * 2 + 1) * 32 + lane];
        int4  wn[4];
        #pragma unroll
        for (int j = 0; j < 4; j++)
            wn[j] = *(const int4*)(wrow + (size_t)j * 8 * IN_F + kofn);

        // compute on current buffers
        #pragma unroll
        for (int j = 0; j < 4; j++) {
            uint32_t b0 = pack_w_h2(wc[j].x, wc[j].y);
            uint32_t b1 = pack_w_h2(wc[j].z, wc[j].w);
            mma16816(c[0][j], A0c.x, A0c.y, A0c.z, A0c.w, b0, b1);
            mma16816(c[1][j], A1c.x, A1c.y, A1c.z, A1c.w, b0, b1);
        }

        // rotate buffers
        A0c = A0n; A1c = A1n;
        #pragma unroll
        for (int j = 0; j < 4; j++) wc[j] = wn[j];
    }

    // cross-warp K reduction through smem (8 partials)
    __shared__ float red[NWARPS][TOKENS][32];
    #pragma unroll
    for (int mi = 0; mi < 2; mi++) {
        #pragma unroll
        for (int j = 0; j < 4; j++) {
            int row = mi * 16 + g;
            int col = j * 8 + 2 * q;
            *(float2*)&red[warp][row][col]     = make_float2(c[mi][j][0], c[mi][j][1]);
            *(float2*)&red[warp][row + 8][col] = make_float2(c[mi][j][2], c[mi][j][3]);
        }
    }
    __syncthreads();

    // 256 threads: each stores 4 (row,col) outputs
    const int col   = threadIdx.x & 31;
    const int rbase = (threadIdx.x >> 5) * 4;
    #pragma unroll
    for (int i = 0; i < 4; i++) {
        int row = rbase + i;
        float v = 0.0f;
        #pragma unroll
        for (int w = 0; w < NWARPS; w++) v += red[w][row][col];
        out[(size_t)row * OUT_F + n0 + col] = v;
    }
}

// ---------------------------------------------------------------------------
extern "C" void kernel_launch(void* const* d_in, const int* in_sizes, int n_in,
                              void* d_out, int out_size)
{
    const float* x      = (const float*)d_in[0];
    const int*   weight = (const int*)d_in[1];
    const float* scales = (const float*)d_in[2];
    float*       out    = (float*)d_out;

    prep_xs_kernel<<<64, 256>>>(x, scales);

    // launch gemm as a programmatic dependent of prep (overlap prologue)
    cudaLaunchConfig_t cfg = {};
    cfg.gridDim  = dim3(OUT_F / 32, 1, 1);
    cfg.blockDim = dim3(256, 1, 1);
    cfg.dynamicSmemBytes = 0;
    cfg.stream = 0;
    cudaLaunchAttribute attr[1];
    attr[0].id = cudaLaunchAttributeProgrammaticStreamSerialization;
    attr[0].val.programmaticStreamSerializationAllowed = 1;
    cfg.attrs = attr;
    cfg.numAttrs = 1;
    cudaLaunchKernelEx(&cfg, gemm_q8_kernel, weight, out);
}